// round 1
// baseline (speedup 1.0000x reference)
#include <cuda_runtime.h>

static constexpr int SEQ_LEN = 128;
static constexpr int BATCH   = 65536;

__global__ __launch_bounds__(256) void fsrs_kernel(
    const float* __restrict__ inp,   // (SEQ_LEN, BATCH, 2) float32
    const float* __restrict__ w,     // (17,) float32
    float*       __restrict__ out,   // outputs (SEQ_LEN, BATCH, 2) [+ final (BATCH,2)]
    long long out_elems)
{
    const int b = blockIdx.x * blockDim.x + threadIdx.x;
    if (b >= BATCH) return;

    const float w0 = w[0],  w1 = w[1],  w2 = w[2],  w3 = w[3];
    const float w4 = w[4],  w5 = w[5],  w6 = w[6],  w7 = w[7];
    const float w8 = w[8],  w9 = w[9],  w10 = w[10], w11 = w[11];
    const float w12 = w[12], w13 = w[13], w14 = w[14], w15 = w[15], w16 = w[16];

    const float LOG2E = 1.4426950408889634f;
    const float ew8   = exp2f(w8 * LOG2E);   // exp(w8), loop-invariant
    const float w10l  = w10 * LOG2E;
    const float w14l  = w14 * LOG2E;
    const float c_d1  = w7 * w4;             // mean-reversion constants
    const float c_d2  = 1.0f - w7;

    const float2* in2  = (const float2*)inp;
    float2*       out2 = (float2*)out;

    // ---- first step ----
    float2 x0 = in2[b];                      // (t, rating) at step 0
    float rating0 = x0.y;
    int ridx = (int)rating0 - 1;
    ridx = max(0, min(3, ridx));
    bool valid = (rating0 >= 1.0f) && (rating0 <= 4.0f);
    float s = (ridx == 0) ? w0 : (ridx == 1) ? w1 : (ridx == 2) ? w2 : w3;
    if (!valid) s = 1.0f;
    float d = fminf(10.0f, fmaxf(1.0f, w4 - w5 * (rating0 - 3.0f)));
    s = fminf(36500.0f, fmaxf(0.01f, s));
    out2[b] = make_float2(s, d);

    // ---- scan over steps 1..127 ----
    #pragma unroll 4
    for (int n = 1; n < SEQ_LEN; ++n) {
        float2 x = in2[n * BATCH + b];
        float t  = x.x;
        float rt = x.y;

        // r = 9s / (9s + t)
        float denom = fmaf(9.0f, s, t);
        float r   = __fdividef(9.0f * s, denom);
        float omr = 1.0f - r;

        float hp = (rt == 2.0f) ? w15 : 1.0f;
        float eb = (rt == 4.0f) ? w16 : 1.0f;

        // success branch: s * (1 + e^w8 * (11-d) * s^-w9 * (e^{(1-r)w10}-1) * hp * eb)
        float pw  = exp2f(-w9 * __log2f(s));
        float e1  = exp2f(omr * w10l) - 1.0f;
        float fac = ew8 * (11.0f - d) * pw * e1 * hp * eb;
        float s_succ = fmaf(s, fac, s);

        // failure branch: min(w11 * d^-w12 * ((s+1)^w13 - 1) * e^{(1-r)w14}, s)
        float pd = exp2f(-w12 * __log2f(d));
        float ps = exp2f(w13 * __log2f(s + 1.0f)) - 1.0f;
        float e2 = exp2f(omr * w14l);
        float s_fail = fminf(w11 * pd * ps * e2, s);

        float ns = (rt > 1.0f) ? s_succ : s_fail;

        float nd = fmaf(-w6, rt - 3.0f, d);      // d - w6*(rating-3)
        nd = fmaf(c_d2, nd, c_d1);               // w7*w4 + (1-w7)*nd
        nd = fminf(10.0f, fmaxf(1.0f, nd));
        ns = fminf(36500.0f, fmaxf(0.01f, ns));

        s = ns;
        d = nd;
        out2[n * BATCH + b] = make_float2(s, d);
    }

    // ---- final_state (second output tensor), if the buffer includes it ----
    if (out_elems >= (long long)(SEQ_LEN + 1) * BATCH * 2) {
        out2[SEQ_LEN * BATCH + b] = make_float2(s, d);
    }
}

extern "C" void kernel_launch(void* const* d_in, const int* in_sizes, int n_in,
                              void* d_out, int out_size)
{
    const float* inputs = (const float*)d_in[0];   // (128, 65536, 2) f32
    const float* w      = (const float*)d_in[1];   // (17,) f32
    float* out          = (float*)d_out;

    dim3 block(256);
    dim3 grid(BATCH / 256);
    fsrs_kernel<<<grid, block>>>(inputs, w, out, (long long)out_size);
}